// round 1
// baseline (speedup 1.0000x reference)
#include <cuda_runtime.h>
#include <math.h>

#define BN 4
#define IH 512
#define IW 512

// ---------------- static scratch (no runtime allocation allowed) ----------------
__device__ float g_pA[BN*2*IH*IW];        // TV dual variable, ping
__device__ float g_pB[BN*2*IH*IW];        // TV dual variable, pong
__device__ float g_den[BN*IH*IW];         // denoised image
__device__ float g_bufA[8*1024*1024];     // 32MB ping buffer
__device__ float g_bufB[4*1024*1024];     // 16MB pong buffer
__device__ float g_weff[1281];            // folded proj/final weights + beta
__device__ float g_s[BN*256];             // scalar field s[b,16,16]

__device__ __forceinline__ float silu(float x){ return x/(1.f+__expf(-x)); }

// ---------------- TV Chambolle: one fused iteration (halo-tiled) ----------------
__global__ void tv_iter_k(const float* __restrict__ img,
                          const float* __restrict__ pin,
                          float* __restrict__ pout){
    const int b  = blockIdx.z;
    const int r0 = blockIdx.y*32, c0 = blockIdx.x*32;
    __shared__ float sp0[34*34], sp1[34*34], so[33*34];
    const float* ib = img + b*IH*IW;
    const float* p0 = pin + (b*2+0)*IH*IW;
    const float* p1 = pin + (b*2+1)*IH*IW;
    const int tid = threadIdx.x;

    // load p with 1-pixel halo (0 outside image == correct boundary behavior)
    for(int i=tid;i<34*34;i+=256){
        int ly=i/34, lx=i%34;
        int gy=r0+ly-1, gx=c0+lx-1;
        bool in = (gy>=0 && gy<IH && gx>=0 && gx<IW);
        sp0[i] = in ? p0[gy*IW+gx] : 0.f;
        sp1[i] = in ? p1[gy*IW+gx] : 0.f;
    }
    __syncthreads();

    // out = image + div(p) on tile + (bottom,right) ring
    for(int i=tid;i<33*33;i+=256){
        int ly=i/33, lx=i%33;
        int gy=r0+ly, gx=c0+lx;
        float v = 0.f;
        if(gy<IH && gx<IW){
            int s = (ly+1)*34 + (lx+1);
            v = ib[gy*IW+gx] - sp0[s] - sp1[s] + sp0[s-34] + sp1[s-1];
        }
        so[ly*34+lx] = v;
    }
    __syncthreads();

    float* q0 = pout + (b*2+0)*IH*IW;
    float* q1 = pout + (b*2+1)*IH*IW;
    for(int i=tid;i<32*32;i+=256){
        int ty=i/32, tx=i%32;
        int gy=r0+ty, gx=c0+tx;
        float o   = so[ty*34+tx];
        float gyv = (gy<IH-1) ? so[(ty+1)*34+tx]-o : 0.f;
        float gxv = (gx<IW-1) ? so[ty*34+tx+1]-o : 0.f;
        float nrm = sqrtf(gyv*gyv + gxv*gxv);
        float inv = 1.f/(1.f + 2.5f*nrm);          // tau/weight = 0.25/0.1
        int s = (ty+1)*34+(tx+1);
        q0[gy*IW+gx] = (sp0[s] - 0.25f*gyv)*inv;
        q1[gy*IW+gx] = (sp1[s] - 0.25f*gxv)*inv;
    }
}

// denoised = image + div(p)
__global__ void tv_final_k(const float* __restrict__ img,
                           const float* __restrict__ p,
                           float* __restrict__ den){
    int idx = blockIdx.x*256 + threadIdx.x;
    if(idx >= BN*IH*IW) return;
    int b = idx/(IH*IW); int r = idx%(IH*IW); int y=r/IW, x=r%IW;
    const float* p0 = p + (b*2)*IH*IW;
    const float* p1 = p0 + IH*IW;
    float d = -p0[r]-p1[r];
    if(y>0) d += p0[r-IW];
    if(x>0) d += p1[r-1];
    den[idx] = img[idx] + d;
}

// ---------------- stem: 1->32ch 3x3 stride2 + silu ----------------
__global__ void stem_k(const float* __restrict__ x, const float* __restrict__ w,
                       float* __restrict__ y){
    __shared__ float sw[288];
    for(int i=threadIdx.x;i<288;i+=256) sw[i]=w[i];
    __syncthreads();
    int idx = blockIdx.x*256 + threadIdx.x;     // B*256*256
    int b = idx>>16; int r = idx & 65535; int oy=r>>8, ox=r&255;
    const float* xb = x + b*IH*IW;
    float patch[9];
#pragma unroll
    for(int ky=0;ky<3;ky++)
#pragma unroll
    for(int kx=0;kx<3;kx++){
        int iy=2*oy-1+ky, ix=2*ox-1+kx;
        patch[ky*3+kx] = (iy>=0&&iy<IH&&ix>=0&&ix<IW)? xb[iy*IW+ix] : 0.f;
    }
    float* yb = y + (size_t)(b*32)*65536 + oy*256 + ox;
#pragma unroll
    for(int c=0;c<32;c++){
        float acc=0.f;
#pragma unroll
        for(int k=0;k<9;k++) acc += patch[k]*sw[c*9+k];
        yb[c*65536] = silu(acc);
    }
}

// ---------------- depthwise 3x3 stride2 + silu ----------------
__global__ void dw_k(const float* __restrict__ x, const float* __restrict__ w,
                     float* __restrict__ y, int C, int Hi, int Ho){
    int idx = blockIdx.x*256 + threadIdx.x;
    if(idx >= BN*C*Ho*Ho) return;
    int ox = idx % Ho; int t = idx/Ho; int oy=t%Ho; t/=Ho; int c=t%C; int b=t/C;
    const float* xb = x + (size_t)(b*C+c)*Hi*Hi;
    const float* wc = w + c*9;
    float acc=0.f;
#pragma unroll
    for(int ky=0;ky<3;ky++){
        int iy=2*oy-1+ky; if(iy<0||iy>=Hi) continue;
#pragma unroll
        for(int kx=0;kx<3;kx++){
            int ix=2*ox-1+kx; if(ix<0||ix>=Hi) continue;
            acc += xb[iy*Hi+ix]*wc[ky*3+kx];
        }
    }
    y[idx] = silu(acc);
}

// ---------------- pointwise 1x1 + silu: GEMM M(Co) x N(pix) x K(Ci) ----------------
__global__ void pw_k(const float* __restrict__ x, const float* __restrict__ w,
                     float* __restrict__ y, int M, int K, int HW){
    int b = blockIdx.z, m0 = blockIdx.y*64, p0 = blockIdx.x*64;
    __shared__ float As[16][64];
    __shared__ float Bs[16][64];
    int tid = threadIdx.x;
    int tr = tid>>4, tc = tid&15;
    float acc[4][4] = {};
    const float* xb = x + (size_t)b*K*HW;
    for(int k0=0;k0<K;k0+=16){
#pragma unroll
        for(int r=0;r<4;r++){
            int id = tid + 256*r;
            int m  = id>>4, kk = id&15;
            As[kk][m] = w[(m0+m)*K + k0 + kk];
            int kk2 = id>>6, p = id&63;
            Bs[kk2][p] = xb[(size_t)(k0+kk2)*HW + p0 + p];
        }
        __syncthreads();
#pragma unroll
        for(int kk=0;kk<16;kk++){
            float a0=As[kk][tr*4+0], a1=As[kk][tr*4+1], a2=As[kk][tr*4+2], a3=As[kk][tr*4+3];
            float b0=Bs[kk][tc*4+0], b1=Bs[kk][tc*4+1], b2=Bs[kk][tc*4+2], b3=Bs[kk][tc*4+3];
            acc[0][0]+=a0*b0; acc[0][1]+=a0*b1; acc[0][2]+=a0*b2; acc[0][3]+=a0*b3;
            acc[1][0]+=a1*b0; acc[1][1]+=a1*b1; acc[1][2]+=a1*b2; acc[1][3]+=a1*b3;
            acc[2][0]+=a2*b0; acc[2][1]+=a2*b1; acc[2][2]+=a2*b2; acc[2][3]+=a2*b3;
            acc[3][0]+=a3*b0; acc[3][1]+=a3*b1; acc[3][2]+=a3*b2; acc[3][3]+=a3*b3;
        }
        __syncthreads();
    }
#pragma unroll
    for(int i=0;i<4;i++)
#pragma unroll
    for(int j=0;j<4;j++)
        y[(size_t)(b*M + m0 + tr*4+i)*HW + p0 + tc*4+j] = silu(acc[i][j]);
}

// ---------------- fold final_w . proj_w -> w_eff[1280], beta -> w_eff[1280] ----------------
__global__ void weff_k(const float* __restrict__ proj_w, const float* __restrict__ proj_b,
                       const float* __restrict__ final_w, float* __restrict__ out){
    int k = blockIdx.x*256 + threadIdx.x;
    if(k < 1280){
        float acc=0.f;
        for(int c=0;c<64;c++) acc += final_w[c]*proj_w[c*1280 + k];
        out[k]=acc;
    }
    if(k == 1280){
        float acc=0.f;
        for(int c=0;c<64;c++) acc += final_w[c]*proj_b[c];
        out[1280]=acc;
    }
}

// ---------------- s[b,p] = sum_k w_eff[k]*head[b,k,p] + beta ----------------
__global__ void s_k(const float* __restrict__ head, const float* __restrict__ weff,
                    float* __restrict__ s){
    __shared__ float sw[1280];
    int b = blockIdx.x, tid = threadIdx.x;
    for(int i=tid;i<1280;i+=256) sw[i]=weff[i];
    __syncthreads();
    const float* hb = head + (size_t)b*1280*256 + tid;
    float acc = weff[1280];
    for(int k=0;k<1280;k++) acc += sw[k]*hb[(size_t)k*256];
    s[b*256+tid] = acc;
}

// ---------------- out = 0.25*sum_{4x4} clamped-bilinear(s) + final_b ----------------
__global__ void final_k(const float* __restrict__ s, const float* __restrict__ final_b,
                        float* __restrict__ out){
    int b = blockIdx.x >> 6;          // 64 blocks per image (128*128/256)
    __shared__ float ss[256];
    int tid = threadIdx.x;
    ss[tid] = s[b*256 + tid];
    __syncthreads();
    int idx = blockIdx.x*256 + tid;
    int r = idx & 16383; int i = r>>7, j = r&127;
    float acc = 0.f;
#pragma unroll
    for(int dy=0;dy<4;dy++){
        float fy  = (4*i+dy+0.5f)*(1.f/32.f) - 0.5f;
        float y0f = floorf(fy); float f = fy - y0f;
        int y0 = (int)y0f;
        int iy0 = min(max(y0,0),15), iy1 = min(max(y0+1,0),15);
#pragma unroll
        for(int dx=0;dx<4;dx++){
            float fx  = (4*j+dx+0.5f)*(1.f/32.f) - 0.5f;
            float x0f = floorf(fx); float g = fx - x0f;
            int x0 = (int)x0f;
            int ix0 = min(max(x0,0),15), ix1 = min(max(x0+1,0),15);
            float top = ss[iy0*16+ix0]*(1.f-g) + ss[iy0*16+ix1]*g;
            float bot = ss[iy1*16+ix0]*(1.f-g) + ss[iy1*16+ix1]*g;
            acc += top*(1.f-f) + bot*f;
        }
    }
    out[idx] = 0.25f*acc + final_b[0];
}

// ---------------- launch ----------------
extern "C" void kernel_launch(void* const* d_in, const int* in_sizes, int n_in,
                              void* d_out, int out_size){
    const float* img     = (const float*)d_in[0];
    const float* stem_w  = (const float*)d_in[1];
    const float* dw1_w   = (const float*)d_in[2];
    const float* pw1_w   = (const float*)d_in[3];
    const float* dw2_w   = (const float*)d_in[4];
    const float* pw2_w   = (const float*)d_in[5];
    const float* dw3_w   = (const float*)d_in[6];
    const float* pw3_w   = (const float*)d_in[7];
    const float* dw4_w   = (const float*)d_in[8];
    const float* pw4_w   = (const float*)d_in[9];
    const float* head_w  = (const float*)d_in[10];
    const float* proj_w  = (const float*)d_in[11];
    const float* proj_b  = (const float*)d_in[12];
    const float* final_w = (const float*)d_in[13];
    const float* final_b = (const float*)d_in[14];

    float *pA,*pB,*den,*bA,*bB,*weff,*sbuf;
    cudaGetSymbolAddress((void**)&pA,  g_pA);
    cudaGetSymbolAddress((void**)&pB,  g_pB);
    cudaGetSymbolAddress((void**)&den, g_den);
    cudaGetSymbolAddress((void**)&bA,  g_bufA);
    cudaGetSymbolAddress((void**)&bB,  g_bufB);
    cudaGetSymbolAddress((void**)&weff,g_weff);
    cudaGetSymbolAddress((void**)&sbuf,g_s);

    // p = 0
    cudaMemsetAsync(pA, 0, (size_t)BN*2*IH*IW*sizeof(float));

    // 20 TV iterations, ping-pong
    dim3 tvg(16,16,BN);
    for(int t=0;t<20;t++){
        const float* in = (t&1)? pB : pA;
        float*       ot = (t&1)? pA : pB;
        tv_iter_k<<<tvg,256>>>(img, in, ot);
    }
    tv_final_k<<<(BN*IH*IW)/256,256>>>(img, pA, den);   // t=19 wrote pA

    // backbone
    stem_k<<<(BN*256*256)/256,256>>>(den, stem_w, bA);                  // [4,32,256,256]
    dw_k<<<(BN*32*128*128)/256,256>>>(bA, dw1_w, bB, 32, 256, 128);     // [4,32,128,128]
    pw_k<<<dim3(16384/64, 64/64,  BN),256>>>(bB, pw1_w, bA, 64,  32, 16384);
    dw_k<<<(BN*64*64*64)/256,256>>>(bA, dw2_w, bB, 64, 128, 64);        // [4,64,64,64]
    pw_k<<<dim3(4096/64, 128/64,  BN),256>>>(bB, pw2_w, bA, 128, 64, 4096);
    dw_k<<<(BN*128*32*32)/256,256>>>(bA, dw3_w, bB, 128, 64, 32);       // [4,128,32,32]
    pw_k<<<dim3(1024/64, 256/64,  BN),256>>>(bB, pw3_w, bA, 256, 128, 1024);
    dw_k<<<(BN*256*16*16)/256,256>>>(bA, dw4_w, bB, 256, 32, 16);       // [4,256,16,16]
    pw_k<<<dim3(256/64,  512/64,  BN),256>>>(bB, pw4_w, bA, 512, 256, 256);
    pw_k<<<dim3(256/64, 1280/64,  BN),256>>>(bA, head_w, bB, 1280, 512, 256);  // head+silu

    // folded tail
    weff_k<<<6,256>>>(proj_w, proj_b, final_w, weff);
    s_k<<<BN,256>>>(bB, weff, sbuf);
    final_k<<<BN*64,256>>>(sbuf, final_b, (float*)d_out);
}